// round 1
// baseline (speedup 1.0000x reference)
#include <cuda_runtime.h>
#include <math.h>

// ---------------------------------------------------------------------------
// SwinBlock: LN1 -> shifted-window MHA (+rel pos bias) -> proj -> residual
//            -> LN2 -> fc1 -> GELU -> fc2 -> residual
// Shapes: B=16, H=W=56, C=192, heads=6 (hd=32), WS=7, SHIFT=3, HIDDEN=1152
// ---------------------------------------------------------------------------

#define WSZ    7
#define SHIFT  3
#define HEADS  6
#define DIM    192
#define HIDDEN 1152
#define EPS    1e-5f
#define IMG    56
#define NTOK   49          // WS*WS
#define MAXM   50176       // 16 * 56 * 56 rows

// Scratch (static device globals; no allocation in kernel_launch)
__device__ float g_hwin[(size_t)MAXM * DIM];     // LN1 out, window layout / reused for LN2 out
__device__ float g_qkv [(size_t)MAXM * 3 * DIM]; // QKV
__device__ float g_attn[(size_t)MAXM * DIM];     // attention out, window layout
__device__ float g_x2  [(size_t)MAXM * DIM];     // x + proj (original layout)
__device__ float g_hid [(size_t)MAXM * HIDDEN];  // gelu(fc1)

// Map a row in window layout -> row in original (B, H*W) layout,
// accounting for the cyclic shift (roll by -SHIFT before partition).
__device__ __forceinline__ int win_to_orig(int r) {
    int w   = r / NTOK;
    int n   = r - w * NTOK;
    int b   = w >> 6;          // 64 windows per image (8x8)
    int win = w & 63;
    int hs  = (win >> 3) * WSZ + n / WSZ;   // shifted-image coords
    int ws  = (win & 7)  * WSZ + n % WSZ;
    int h   = hs + SHIFT; if (h >= IMG) h -= IMG;   // orig = shifted + SHIFT (mod 56)
    int x   = ws + SHIFT; if (x >= IMG) x -= IMG;
    return b * (IMG * IMG) + h * IMG + x;
}

// ---------------------------------------------------------------------------
// LayerNorm: one warp per row of 192. remap!=0: output row r (window layout)
// reads source row win_to_orig(r) of `in` (original layout).
// ---------------------------------------------------------------------------
__global__ void ln_kernel(const float* __restrict__ in, float* __restrict__ out,
                          const float* __restrict__ gam, const float* __restrict__ bet,
                          int M, int remap) {
    int r = blockIdx.x * (blockDim.x >> 5) + (threadIdx.x >> 5);
    if (r >= M) return;
    int lane = threadIdx.x & 31;
    int src  = remap ? win_to_orig(r) : r;
    const float* row = in + (size_t)src * DIM;

    float v[6];
    float s = 0.f;
#pragma unroll
    for (int j = 0; j < 6; j++) { v[j] = row[lane + 32 * j]; s += v[j]; }
#pragma unroll
    for (int o = 16; o; o >>= 1) s += __shfl_xor_sync(0xFFFFFFFFu, s, o);
    float mean = s * (1.f / DIM);

    float vs = 0.f;
#pragma unroll
    for (int j = 0; j < 6; j++) { float d = v[j] - mean; vs += d * d; }
#pragma unroll
    for (int o = 16; o; o >>= 1) vs += __shfl_xor_sync(0xFFFFFFFFu, vs, o);
    float rstd = rsqrtf(vs * (1.f / DIM) + EPS);

    float* orow = out + (size_t)r * DIM;
#pragma unroll
    for (int j = 0; j < 6; j++) {
        int c = lane + 32 * j;
        orow[c] = (v[j] - mean) * rstd * gam[c] + bet[c];
    }
}

// ---------------------------------------------------------------------------
// Tiled GEMM: C[M,N] = A[M,K] @ W[N,K]^T + bias, 64x64 tile, BK=16,
// 256 threads, 4x4 outputs/thread. All dims divide tiles exactly.
// MODE 0: plain store
// MODE 1: row-remap (window->orig) + residual add `res` (orig layout), N==192
// MODE 2: exact GELU epilogue
// MODE 3: residual add `res[r]` then store (N==192)
// ---------------------------------------------------------------------------
template <int MODE>
__global__ void gemm_kernel(const float* __restrict__ A, const float* __restrict__ W,
                            const float* __restrict__ bias, float* __restrict__ C,
                            const float* __restrict__ res, int N, int K) {
    __shared__ float As[16][68];
    __shared__ float Bs[16][68];

    const int m0 = blockIdx.y * 64;
    const int n0 = blockIdx.x * 64;
    const int t  = threadIdx.x;          // 0..255
    const int lm = t >> 2;               // 0..63 (row within tile for loads)
    const int kq = t & 3;                // which float4 of the 16-k slab
    const int tx = t & 15;
    const int ty = t >> 4;

    float acc[4][4] = {};

    for (int k0 = 0; k0 < K; k0 += 16) {
        float4 a4 = *(const float4*)(A + (size_t)(m0 + lm) * K + k0 + kq * 4);
        float4 b4 = *(const float4*)(W + (size_t)(n0 + lm) * K + k0 + kq * 4);
        As[kq * 4 + 0][lm] = a4.x; As[kq * 4 + 1][lm] = a4.y;
        As[kq * 4 + 2][lm] = a4.z; As[kq * 4 + 3][lm] = a4.w;
        Bs[kq * 4 + 0][lm] = b4.x; Bs[kq * 4 + 1][lm] = b4.y;
        Bs[kq * 4 + 2][lm] = b4.z; Bs[kq * 4 + 3][lm] = b4.w;
        __syncthreads();
#pragma unroll
        for (int kk = 0; kk < 16; kk++) {
            float av[4], bv[4];
#pragma unroll
            for (int i = 0; i < 4; i++) av[i] = As[kk][ty * 4 + i];
#pragma unroll
            for (int j = 0; j < 4; j++) bv[j] = Bs[kk][tx * 4 + j];
#pragma unroll
            for (int i = 0; i < 4; i++)
#pragma unroll
                for (int j = 0; j < 4; j++) acc[i][j] = fmaf(av[i], bv[j], acc[i][j]);
        }
        __syncthreads();
    }

#pragma unroll
    for (int i = 0; i < 4; i++) {
        int r = m0 + ty * 4 + i;
        int orow = (MODE == 1) ? win_to_orig(r) : r;
#pragma unroll
        for (int j = 0; j < 4; j++) {
            int c = n0 + tx * 4 + j;
            float v = acc[i][j] + bias[c];
            if (MODE == 0) {
                C[(size_t)r * N + c] = v;
            } else if (MODE == 1) {
                size_t o = (size_t)orow * DIM + c;
                C[o] = v + res[o];
            } else if (MODE == 2) {
                C[(size_t)r * N + c] = 0.5f * v * (1.0f + erff(v * 0.70710678118654752f));
            } else { // MODE 3
                size_t o = (size_t)r * DIM + c;
                C[o] = v + res[o];
            }
        }
    }
}

// ---------------------------------------------------------------------------
// Windowed attention: one block per (window, head). 64 threads.
// q,k,v (49x32) in smem; softmax(QK^T*scale + relposbias) @ V.
// ---------------------------------------------------------------------------
__global__ void attn_kernel(const float* __restrict__ qkv,
                            const float* __restrict__ rpb,
                            float* __restrict__ out) {
    __shared__ float q[NTOK][33], k[NTOK][33], v[NTOK][33];
    __shared__ float at[NTOK][51];
    __shared__ float bsh[169];

    const int w    = blockIdx.x / HEADS;
    const int head = blockIdx.x % HEADS;
    const int t    = threadIdx.x;   // 0..63

    const float* base = qkv + (size_t)w * NTOK * (3 * DIM) + head * 32;
    for (int idx = t; idx < NTOK * 32 * 3; idx += 64) {
        int part = idx / (NTOK * 32);
        int rem  = idx - part * NTOK * 32;
        int n = rem >> 5, d = rem & 31;
        float val = base[(size_t)n * (3 * DIM) + part * DIM + d];
        if      (part == 0) q[n][d] = val;
        else if (part == 1) k[n][d] = val;
        else                v[n][d] = val;
    }
    for (int idx = t; idx < 169; idx += 64) bsh[idx] = rpb[idx * HEADS + head];
    __syncthreads();

    if (t < NTOK) {
        const float scale = 0.17677669529663687f;  // 32^-0.5
        int pin = t / WSZ, pjn = t % WSZ;
        float mx = -1e30f;
#pragma unroll 7
        for (int m = 0; m < NTOK; m++) {
            float s = 0.f;
#pragma unroll
            for (int d = 0; d < 32; d++) s = fmaf(q[t][d], k[m][d], s);
            int idx = (pin - m / WSZ + 6) * 13 + (pjn - m % WSZ + 6);
            s = s * scale + bsh[idx];
            at[t][m] = s;
            mx = fmaxf(mx, s);
        }
        float sum = 0.f;
#pragma unroll 7
        for (int m = 0; m < NTOK; m++) {
            float e = __expf(at[t][m] - mx);
            at[t][m] = e;
            sum += e;
        }
        float inv = 1.0f / sum;
        float* orow = out + ((size_t)(w * NTOK + t) * DIM + head * 32);
#pragma unroll
        for (int d = 0; d < 32; d++) {
            float o = 0.f;
#pragma unroll 7
            for (int m = 0; m < NTOK; m++) o = fmaf(at[t][m], v[m][d], o);
            orow[d] = o * inv;
        }
    }
}

// ---------------------------------------------------------------------------
extern "C" void kernel_launch(void* const* d_in, const int* in_sizes, int n_in,
                              void* d_out, int out_size) {
    const float* x = (const float*)d_in[0];
    // Handle both cases: scalar ints H,W present as inputs (16 total) or not (14).
    int base = n_in - 13;  // index of ln1_g
    const float* ln1_g  = (const float*)d_in[base + 0];
    const float* ln1_b  = (const float*)d_in[base + 1];
    const float* qkv_w  = (const float*)d_in[base + 2];
    const float* qkv_b  = (const float*)d_in[base + 3];
    const float* rpb    = (const float*)d_in[base + 4];
    const float* proj_w = (const float*)d_in[base + 5];
    const float* proj_b = (const float*)d_in[base + 6];
    const float* ln2_g  = (const float*)d_in[base + 7];
    const float* ln2_b  = (const float*)d_in[base + 8];
    const float* fc1_w  = (const float*)d_in[base + 9];
    const float* fc1_b  = (const float*)d_in[base + 10];
    const float* fc2_w  = (const float*)d_in[base + 11];
    const float* fc2_b  = (const float*)d_in[base + 12];

    const int Bsz = in_sizes[0] / (IMG * IMG * DIM);
    const int M   = Bsz * IMG * IMG;          // 50176 rows

    float *hwin, *qkv, *attn, *x2, *hid;
    cudaGetSymbolAddress((void**)&hwin, g_hwin);
    cudaGetSymbolAddress((void**)&qkv,  g_qkv);
    cudaGetSymbolAddress((void**)&attn, g_attn);
    cudaGetSymbolAddress((void**)&x2,   g_x2);
    cudaGetSymbolAddress((void**)&hid,  g_hid);

    const int lnGrid = (M + 7) / 8;           // 8 warps (rows) per 256-thread block
    const int mTiles = M / 64;

    // 1. LN1 fused with shift + window partition (writes window layout)
    ln_kernel<<<lnGrid, 256>>>(x, hwin, ln1_g, ln1_b, M, 1);
    // 2. QKV GEMM
    gemm_kernel<0><<<dim3(576 / 64, mTiles), 256>>>(hwin, qkv_w, qkv_b, qkv, nullptr, 576, DIM);
    // 3. Windowed attention + relative position bias
    attn_kernel<<<(M / NTOK) * HEADS, 64>>>(qkv, rpb, attn);
    // 4. proj GEMM fused with window-reverse + unshift + residual (-> x2, orig layout)
    gemm_kernel<1><<<dim3(DIM / 64, mTiles), 256>>>(attn, proj_w, proj_b, x2, x, DIM, DIM);
    // 5. LN2 (plain layout)
    ln_kernel<<<lnGrid, 256>>>(x2, hwin, ln2_g, ln2_b, M, 0);
    // 6. fc1 GEMM + exact GELU
    gemm_kernel<2><<<dim3(HIDDEN / 64, mTiles), 256>>>(hwin, fc1_w, fc1_b, hid, nullptr, HIDDEN, DIM);
    // 7. fc2 GEMM + residual -> d_out
    gemm_kernel<3><<<dim3(DIM / 64, mTiles), 256>>>(hid, fc2_w, fc2_b, (float*)d_out, x2, DIM, HIDDEN);
}

// round 4
// speedup vs baseline: 1.5854x; 1.5854x over previous
#include <cuda_runtime.h>
#include <cuda_bf16.h>
#include <cstdint>
#include <math.h>

// ---------------------------------------------------------------------------
// SwinBlock on sm_103a — bf16x3 tensor-core GEMMs (hi/lo split, fp32 accum).
// Shapes: B=16, H=W=56, C=192, heads=6 (hd=32), WS=7, SHIFT=3, HIDDEN=1152
// ---------------------------------------------------------------------------

#define WSZ    7
#define SHIFT  3
#define HEADS  6
#define DIM    192
#define HIDDEN 1152
#define EPS    1e-5f
#define IMG    56
#define NTOK   49
#define MAXM   50176   // 16*56*56

typedef __nv_bfloat16 bf16;

// ------------------------- scratch (static device) -------------------------
__device__ float g_qkv [(size_t)MAXM * 3 * DIM]; // qkv fp32 (attention input)
__device__ float g_x2  [(size_t)MAXM * DIM];     // x + proj (orig layout)
__device__ bf16  g_h_hi[(size_t)MAXM * DIM];     // LN out hi (reused LN1/LN2)
__device__ bf16  g_h_lo[(size_t)MAXM * DIM];
__device__ bf16  g_at_hi[(size_t)MAXM * DIM];    // attention out (window layout)
__device__ bf16  g_at_lo[(size_t)MAXM * DIM];
__device__ bf16  g_hid_hi[(size_t)MAXM * HIDDEN];// gelu(fc1) out
__device__ bf16  g_hid_lo[(size_t)MAXM * HIDDEN];
__device__ bf16  g_wq_hi[576 * DIM],      g_wq_lo[576 * DIM];
__device__ bf16  g_wp_hi[DIM * DIM],      g_wp_lo[DIM * DIM];
__device__ bf16  g_w1_hi[HIDDEN * DIM],   g_w1_lo[HIDDEN * DIM];
__device__ bf16  g_w2_hi[DIM * HIDDEN],   g_w2_lo[DIM * HIDDEN];

// window row -> original row (cyclic shift by -SHIFT before partition)
__device__ __forceinline__ int win_to_orig(int r) {
    int w   = r / NTOK;
    int n   = r - w * NTOK;
    int b   = w >> 6;
    int win = w & 63;
    int hs  = (win >> 3) * WSZ + n / WSZ;
    int ws  = (win & 7)  * WSZ + n % WSZ;
    int h   = hs + SHIFT; if (h >= IMG) h -= IMG;
    int x   = ws + SHIFT; if (x >= IMG) x -= IMG;
    return b * (IMG * IMG) + h * IMG + x;
}

__device__ __forceinline__ void split_bf16(float v, bf16& hi, bf16& lo) {
    hi = __float2bfloat16(v);
    lo = __float2bfloat16(v - __bfloat162float(hi));
}

// ------------------------- weight fp32 -> hi/lo bf16 -----------------------
__global__ void conv_kernel(const float* __restrict__ w, bf16* __restrict__ hi,
                            bf16* __restrict__ lo, int n) {
    for (int i = blockIdx.x * blockDim.x + threadIdx.x; i < n; i += gridDim.x * blockDim.x) {
        bf16 h, l; split_bf16(w[i], h, l);
        hi[i] = h; lo[i] = l;
    }
}

// ------------------------- LayerNorm (writes hi/lo bf16) --------------------
__global__ void ln_kernel(const float* __restrict__ in, bf16* __restrict__ ohi,
                          bf16* __restrict__ olo,
                          const float* __restrict__ gam, const float* __restrict__ bet,
                          int M, int remap) {
    int r = blockIdx.x * (blockDim.x >> 5) + (threadIdx.x >> 5);
    if (r >= M) return;
    int lane = threadIdx.x & 31;
    int src  = remap ? win_to_orig(r) : r;
    const float* row = in + (size_t)src * DIM;

    float v[6], s = 0.f;
#pragma unroll
    for (int j = 0; j < 6; j++) { v[j] = row[lane + 32 * j]; s += v[j]; }
#pragma unroll
    for (int o = 16; o; o >>= 1) s += __shfl_xor_sync(0xFFFFFFFFu, s, o);
    float mean = s * (1.f / DIM);
    float vs = 0.f;
#pragma unroll
    for (int j = 0; j < 6; j++) { float d = v[j] - mean; vs += d * d; }
#pragma unroll
    for (int o = 16; o; o >>= 1) vs += __shfl_xor_sync(0xFFFFFFFFu, vs, o);
    float rstd = rsqrtf(vs * (1.f / DIM) + EPS);

    size_t ro = (size_t)r * DIM;
#pragma unroll
    for (int j = 0; j < 6; j++) {
        int c = lane + 32 * j;
        float y = (v[j] - mean) * rstd * gam[c] + bet[c];
        bf16 h, l; split_bf16(y, h, l);
        ohi[ro + c] = h; olo[ro + c] = l;
    }
}

// ------------------------- mma.sync helpers --------------------------------
__device__ __forceinline__ void ldsm4(uint32_t r[4], const bf16* p) {
    uint32_t a = (uint32_t)__cvta_generic_to_shared(p);
    asm volatile("ldmatrix.sync.aligned.m8n8.x4.shared.b16 {%0,%1,%2,%3}, [%4];"
                 : "=r"(r[0]), "=r"(r[1]), "=r"(r[2]), "=r"(r[3]) : "r"(a));
}
__device__ __forceinline__ void mma16816(float c[4], const uint32_t a[4],
                                         uint32_t b0, uint32_t b1) {
    asm volatile(
        "mma.sync.aligned.m16n8k16.row.col.f32.bf16.bf16.f32 "
        "{%0,%1,%2,%3}, {%4,%5,%6,%7}, {%8,%9}, {%0,%1,%2,%3};"
        : "+f"(c[0]), "+f"(c[1]), "+f"(c[2]), "+f"(c[3])
        : "r"(a[0]), "r"(a[1]), "r"(a[2]), "r"(a[3]), "r"(b0), "r"(b1));
}

// ---------------------------------------------------------------------------
// Tensor-core GEMM: C[M,N] = (Ahi+Alo)[M,K] @ (Whi+Wlo)[N,K]^T + bias
// bf16x3: Ahi*Whi + Alo*Whi + Ahi*Wlo, fp32 accumulate.
// BM=128, BN=64, BK=32, 256 threads (8 warps: 4 along M x 2 along N).
// MODE 0: fp32 store (qkv)
// MODE 1: row-remap win->orig + residual -> fp32 (proj)
// MODE 2: GELU -> hi/lo bf16 (fc1)
// MODE 3: residual -> fp32 (fc2 -> d_out)
// ---------------------------------------------------------------------------
#define SKP 40   // padded k-stride (bf16) per 32-k smem row

template <int MODE>
__global__ void __launch_bounds__(256)
gemm_tc(const bf16* __restrict__ Ahi, const bf16* __restrict__ Alo,
        const bf16* __restrict__ Whi, const bf16* __restrict__ Wlo,
        const float* __restrict__ bias, int N, int K,
        float* __restrict__ Cf, bf16* __restrict__ Chi, bf16* __restrict__ Clo,
        const float* __restrict__ res) {
    __shared__ bf16 sm[(128 + 128 + 64 + 64) * SKP];
    bf16* sAh = sm;                 // 128*SKP
    bf16* sAl = sm + 128 * SKP;
    bf16* sWh = sm + 256 * SKP;     // 64*SKP
    bf16* sWl = sm + 320 * SKP;

    const int m0 = blockIdx.y * 128, n0 = blockIdx.x * 64;
    const int tid = threadIdx.x, lane = tid & 31, w = tid >> 5;
    const int wm = w & 3, wn = w >> 2;

    float acc[2][4][4] = {};

    for (int k0 = 0; k0 < K; k0 += 32) {
#pragma unroll
        for (int it = 0; it < 2; it++) {
            int c = tid + it * 256;           // 512 A chunks of 16B
            int row = c >> 2, q = c & 3;
            size_t g = (size_t)(m0 + row) * K + k0 + q * 8;
            *(uint4*)&sAh[row * SKP + q * 8] = *(const uint4*)&Ahi[g];
            *(uint4*)&sAl[row * SKP + q * 8] = *(const uint4*)&Alo[g];
        }
        {
            int row = tid >> 2, q = tid & 3;  // 256 W chunks (64 rows)
            size_t g = (size_t)(n0 + row) * K + k0 + q * 8;
            *(uint4*)&sWh[row * SKP + q * 8] = *(const uint4*)&Whi[g];
            *(uint4*)&sWl[row * SKP + q * 8] = *(const uint4*)&Wlo[g];
        }
        __syncthreads();

#pragma unroll
        for (int kk = 0; kk < 2; kk++) {
            const int lrow = lane & 15;
            const int lcol = kk * 16 + (lane >> 4) * 8;
            uint32_t ah[2][4], al[2][4], wh[2][4], wl[2][4];
#pragma unroll
            for (int mi = 0; mi < 2; mi++) {
                const bf16* pa = &sAh[(wm * 32 + mi * 16 + lrow) * SKP + lcol];
                ldsm4(ah[mi], pa);
                ldsm4(al[mi], pa + 128 * SKP);
            }
#pragma unroll
            for (int nj = 0; nj < 2; nj++) {
                const bf16* pw = &sWh[(wn * 32 + nj * 16 + lrow) * SKP + lcol];
                ldsm4(wh[nj], pw);
                ldsm4(wl[nj], pw + 64 * SKP);
            }
#pragma unroll
            for (int mi = 0; mi < 2; mi++)
#pragma unroll
                for (int nj = 0; nj < 2; nj++)
#pragma unroll
                    for (int j = 0; j < 2; j++) {
                        float* c = acc[mi][nj * 2 + j];
                        mma16816(c, ah[mi], wh[nj][j], wh[nj][2 + j]);
                        mma16816(c, al[mi], wh[nj][j], wh[nj][2 + j]);
                        mma16816(c, ah[mi], wl[nj][j], wl[nj][2 + j]);
                    }
        }
        __syncthreads();
    }

    // ---------------- epilogue ----------------
    const int g = lane >> 2, t4 = lane & 3;
#pragma unroll
    for (int mi = 0; mi < 2; mi++) {
#pragma unroll
        for (int half = 0; half < 2; half++) {
            int r = m0 + wm * 32 + mi * 16 + g + half * 8;
            int ro = (MODE == 1) ? win_to_orig(r) : r;
#pragma unroll
            for (int ni = 0; ni < 4; ni++) {
                int cc = n0 + wn * 32 + ni * 8 + t4 * 2;
                float v0 = acc[mi][ni][half * 2 + 0] + bias[cc];
                float v1 = acc[mi][ni][half * 2 + 1] + bias[cc + 1];
                if (MODE == 0) {
                    *(float2*)&Cf[(size_t)r * N + cc] = make_float2(v0, v1);
                } else if (MODE == 1) {
                    size_t o = (size_t)ro * DIM + cc;
                    Cf[o]     = v0 + res[o];
                    Cf[o + 1] = v1 + res[o + 1];
                } else if (MODE == 2) {
                    v0 = 0.5f * v0 * (1.0f + erff(v0 * 0.70710678118654752f));
                    v1 = 0.5f * v1 * (1.0f + erff(v1 * 0.70710678118654752f));
                    bf16 h0, l0, h1, l1;
                    split_bf16(v0, h0, l0); split_bf16(v1, h1, l1);
                    size_t o = (size_t)r * N + cc;
                    *(__nv_bfloat162*)&Chi[o] = __nv_bfloat162(h0, h1);
                    *(__nv_bfloat162*)&Clo[o] = __nv_bfloat162(l0, l1);
                } else { // MODE 3
                    size_t o = (size_t)r * DIM + cc;
                    Cf[o]     = v0 + res[o];
                    Cf[o + 1] = v1 + res[o + 1];
                }
            }
        }
    }
}

// ---------------------------------------------------------------------------
// Windowed attention (fp32): one block per (window, head). 64 threads.
// Writes hi/lo bf16 (window layout) for the proj GEMM.
// ---------------------------------------------------------------------------
__global__ void attn_kernel(const float* __restrict__ qkv,
                            const float* __restrict__ rpb,
                            bf16* __restrict__ ohi, bf16* __restrict__ olo) {
    __shared__ float q[NTOK][33], k[NTOK][33], v[NTOK][33];
    __shared__ float at[NTOK][51];
    __shared__ float bsh[169];

    const int w    = blockIdx.x / HEADS;
    const int head = blockIdx.x % HEADS;
    const int t    = threadIdx.x;

    const float* base = qkv + (size_t)w * NTOK * (3 * DIM) + head * 32;
    for (int idx = t; idx < NTOK * 32 * 3; idx += 64) {
        int part = idx / (NTOK * 32);
        int rem  = idx - part * NTOK * 32;
        int n = rem >> 5, d = rem & 31;
        float val = base[(size_t)n * (3 * DIM) + part * DIM + d];
        if      (part == 0) q[n][d] = val;
        else if (part == 1) k[n][d] = val;
        else                v[n][d] = val;
    }
    for (int idx = t; idx < 169; idx += 64) bsh[idx] = rpb[idx * HEADS + head];
    __syncthreads();

    if (t < NTOK) {
        const float scale = 0.17677669529663687f;
        int pin = t / WSZ, pjn = t % WSZ;
        float mx = -1e30f;
#pragma unroll 7
        for (int m = 0; m < NTOK; m++) {
            float s = 0.f;
#pragma unroll
            for (int d = 0; d < 32; d++) s = fmaf(q[t][d], k[m][d], s);
            int idx = (pin - m / WSZ + 6) * 13 + (pjn - m % WSZ + 6);
            s = s * scale + bsh[idx];
            at[t][m] = s;
            mx = fmaxf(mx, s);
        }
        float sum = 0.f;
#pragma unroll 7
        for (int m = 0; m < NTOK; m++) {
            float e = __expf(at[t][m] - mx);
            at[t][m] = e;
            sum += e;
        }
        float inv = 1.0f / sum;
        size_t orow = (size_t)(w * NTOK + t) * DIM + head * 32;
#pragma unroll
        for (int d = 0; d < 32; d++) {
            float o = 0.f;
#pragma unroll 7
            for (int m = 0; m < NTOK; m++) o = fmaf(at[t][m], v[m][d], o);
            o *= inv;
            bf16 h, l; split_bf16(o, h, l);
            ohi[orow + d] = h; olo[orow + d] = l;
        }
    }
}

// ---------------------------------------------------------------------------
extern "C" void kernel_launch(void* const* d_in, const int* in_sizes, int n_in,
                              void* d_out, int out_size) {
    const float* x = (const float*)d_in[0];
    int base = n_in - 13;
    const float* ln1_g  = (const float*)d_in[base + 0];
    const float* ln1_b  = (const float*)d_in[base + 1];
    const float* qkv_w  = (const float*)d_in[base + 2];
    const float* qkv_b  = (const float*)d_in[base + 3];
    const float* rpb    = (const float*)d_in[base + 4];
    const float* proj_w = (const float*)d_in[base + 5];
    const float* proj_b = (const float*)d_in[base + 6];
    const float* ln2_g  = (const float*)d_in[base + 7];
    const float* ln2_b  = (const float*)d_in[base + 8];
    const float* fc1_w  = (const float*)d_in[base + 9];
    const float* fc1_b  = (const float*)d_in[base + 10];
    const float* fc2_w  = (const float*)d_in[base + 11];
    const float* fc2_b  = (const float*)d_in[base + 12];

    const int Bsz = in_sizes[0] / (IMG * IMG * DIM);
    const int M   = Bsz * IMG * IMG;

    float *qkv, *x2;
    bf16 *h_hi, *h_lo, *at_hi, *at_lo, *hid_hi, *hid_lo;
    bf16 *wq_hi, *wq_lo, *wp_hi, *wp_lo, *w1_hi, *w1_lo, *w2_hi, *w2_lo;
    cudaGetSymbolAddress((void**)&qkv,    g_qkv);
    cudaGetSymbolAddress((void**)&x2,     g_x2);
    cudaGetSymbolAddress((void**)&h_hi,   g_h_hi);
    cudaGetSymbolAddress((void**)&h_lo,   g_h_lo);
    cudaGetSymbolAddress((void**)&at_hi,  g_at_hi);
    cudaGetSymbolAddress((void**)&at_lo,  g_at_lo);
    cudaGetSymbolAddress((void**)&hid_hi, g_hid_hi);
    cudaGetSymbolAddress((void**)&hid_lo, g_hid_lo);
    cudaGetSymbolAddress((void**)&wq_hi,  g_wq_hi);
    cudaGetSymbolAddress((void**)&wq_lo,  g_wq_lo);
    cudaGetSymbolAddress((void**)&wp_hi,  g_wp_hi);
    cudaGetSymbolAddress((void**)&wp_lo,  g_wp_lo);
    cudaGetSymbolAddress((void**)&w1_hi,  g_w1_hi);
    cudaGetSymbolAddress((void**)&w1_lo,  g_w1_lo);
    cudaGetSymbolAddress((void**)&w2_hi,  g_w2_hi);
    cudaGetSymbolAddress((void**)&w2_lo,  g_w2_lo);

    const int lnGrid = (M + 7) / 8;
    const int mT = M / 128;

    // weight conversions
    conv_kernel<<<216, 256>>>(qkv_w,  wq_hi, wq_lo, 576 * DIM);
    conv_kernel<<<72,  256>>>(proj_w, wp_hi, wp_lo, DIM * DIM);
    conv_kernel<<<432, 256>>>(fc1_w,  w1_hi, w1_lo, HIDDEN * DIM);
    conv_kernel<<<432, 256>>>(fc2_w,  w2_hi, w2_lo, DIM * HIDDEN);

    // 1. LN1 fused shift + window partition -> hi/lo
    ln_kernel<<<lnGrid, 256>>>(x, h_hi, h_lo, ln1_g, ln1_b, M, 1);
    // 2. QKV GEMM (fp32 out)
    gemm_tc<0><<<dim3(576 / 64, mT), 256>>>(h_hi, h_lo, wq_hi, wq_lo, qkv_b,
                                            576, DIM, qkv, nullptr, nullptr, nullptr);
    // 3. attention -> hi/lo (window layout)
    attn_kernel<<<(M / NTOK) * HEADS, 64>>>(qkv, rpb, at_hi, at_lo);
    // 4. proj GEMM + window-reverse + residual -> x2 (fp32, orig layout)
    gemm_tc<1><<<dim3(DIM / 64, mT), 256>>>(at_hi, at_lo, wp_hi, wp_lo, proj_b,
                                            DIM, DIM, x2, nullptr, nullptr, x);
    // 5. LN2 -> hi/lo
    ln_kernel<<<lnGrid, 256>>>(x2, h_hi, h_lo, ln2_g, ln2_b, M, 0);
    // 6. fc1 GEMM + GELU -> hi/lo
    gemm_tc<2><<<dim3(HIDDEN / 64, mT), 256>>>(h_hi, h_lo, w1_hi, w1_lo, fc1_b,
                                               HIDDEN, DIM, nullptr, hid_hi, hid_lo, nullptr);
    // 7. fc2 GEMM + residual -> d_out
    gemm_tc<3><<<dim3(DIM / 64, mT), 256>>>(hid_hi, hid_lo, w2_hi, w2_lo, fc2_b,
                                            DIM, HIDDEN, (float*)d_out, nullptr, nullptr, x2);
}